// round 1
// baseline (speedup 1.0000x reference)
#include <cuda_runtime.h>
#include <math.h>
#include <stddef.h>

#define H 100
#define G 400            // 4*H
#define BATCH 512
#define TT 1024
#define FF 64
#define NTOK (BATCH * TT)        // 524288
#define RPB 4                    // batch rows per LSTM CTA
#define LSTM_CTAS (BATCH / RPB)  // 128
#define LSTM_THREADS 400
#define GEMM_ROWS 64
#define GEMM_THREADS 400

// Scratch (static device allocation: no cudaMalloc allowed)
__device__ float g_xw[(size_t)NTOK * G];   // 838.9 MB, reused by both layers
__device__ float g_h1[(size_t)NTOK * H];   // 209.7 MB
__device__ float g_h2last[BATCH * H];

// ---------------------------------------------------------------------------
// Pre-activation GEMM: out[N,400] = A[N,K] @ Wm[K,400] + bias
// Block: 400 threads (one column each) x GEMM_ROWS rows. A tile in SMEM,
// broadcast LDS.128 reads; W streamed through L1 (resident after 1st block).
// ---------------------------------------------------------------------------
template <int K>
__global__ void __launch_bounds__(GEMM_THREADS, 1)
pregemm_kernel(const float* __restrict__ A, const float* __restrict__ Wm,
               const float* __restrict__ bias, float* __restrict__ out)
{
    __shared__ __align__(16) float A_s[GEMM_ROWS * K];
    const int tid = threadIdx.x;
    const size_t row0 = (size_t)blockIdx.x * GEMM_ROWS;

    const float* Atile = A + row0 * K;            // tile is contiguous
    for (int i = tid; i < GEMM_ROWS * K; i += GEMM_THREADS) A_s[i] = Atile[i];
    __syncthreads();

    const int c = tid;  // output column, 0..399
    float acc[GEMM_ROWS];
#pragma unroll
    for (int r = 0; r < GEMM_ROWS; ++r) acc[r] = 0.f;

    for (int k = 0; k < K; k += 4) {
        const float w0 = Wm[(k + 0) * G + c];
        const float w1 = Wm[(k + 1) * G + c];
        const float w2 = Wm[(k + 2) * G + c];
        const float w3 = Wm[(k + 3) * G + c];
#pragma unroll
        for (int r = 0; r < GEMM_ROWS; ++r) {
            float4 a = *(const float4*)&A_s[r * K + k];   // broadcast
            acc[r] = fmaf(a.x, w0, acc[r]);
            acc[r] = fmaf(a.y, w1, acc[r]);
            acc[r] = fmaf(a.z, w2, acc[r]);
            acc[r] = fmaf(a.w, w3, acc[r]);
        }
    }

    const float bc = bias[c];
#pragma unroll 8
    for (int r = 0; r < GEMM_ROWS; ++r)
        out[(row0 + r) * G + c] = acc[r] + bc;
}

__device__ __forceinline__ float sigmoidf_(float x)
{
    return 1.f / (1.f + __expf(-x));
}

// ---------------------------------------------------------------------------
// Persistent LSTM layer: one CTA owns RPB=4 batch rows for all T steps.
// SMEM: U [100x400] (160KB, loaded once), h [100x4] (float4 rows), z [4x400].
// Phase 1 (per step): thread c computes z[r][c] = zpre + sum_k h[r][k]*U[k][c]
// Phase 2: thread (r=tid/100, j=tid%100) applies gates, updates c-state, h.
// ---------------------------------------------------------------------------
template <bool STORE_ALL>
__global__ void __launch_bounds__(LSTM_THREADS, 1)
lstm_kernel(const float* __restrict__ zpre,   // [B,T,G]
            const float* __restrict__ U,      // [H,G]
            float* __restrict__ h_all,        // [B,T,H] (layer 1)
            float* __restrict__ h_last)       // [B,H]   (layer 2)
{
    extern __shared__ __align__(16) float smem[];
    float* U_s = smem;                         // H*G   = 40000 floats
    float* h_s = smem + H * G;                 // H*RPB = 400 floats
    float* z_s = smem + H * G + H * RPB;       // RPB*G = 1600 floats

    const int tid = threadIdx.x;               // 0..399
    const int b0  = blockIdx.x * RPB;

    for (int i = tid; i < H * G; i += LSTM_THREADS) U_s[i] = U[i];
    for (int i = tid; i < H * RPB; i += LSTM_THREADS) h_s[i] = 0.f;

    const int c = tid;          // z-phase column
    const int j = tid % H;      // gate-phase hidden index
    const int r = tid / H;      // gate-phase row
    float c_st = 0.f;
    float h_carry = 0.f;
    __syncthreads();

    const size_t rowstride = (size_t)TT * G;
    for (int t = 0; t < TT; ++t) {
        const size_t base = (size_t)b0 * rowstride + (size_t)t * G + c;
        const float z0 = zpre[base];
        const float z1 = zpre[base + rowstride];
        const float z2 = zpre[base + 2 * rowstride];
        const float z3 = zpre[base + 3 * rowstride];

        float a0 = 0.f, a1 = 0.f, a2 = 0.f, a3 = 0.f;
#pragma unroll
        for (int k = 0; k < H; ++k) {
            const float u = U_s[k * G + c];                       // conflict-free
            const float4 h4 = *(const float4*)&h_s[k * RPB];      // broadcast
            a0 = fmaf(h4.x, u, a0);
            a1 = fmaf(h4.y, u, a1);
            a2 = fmaf(h4.z, u, a2);
            a3 = fmaf(h4.w, u, a3);
        }
        z_s[0 * G + c] = a0 + z0;
        z_s[1 * G + c] = a1 + z1;
        z_s[2 * G + c] = a2 + z2;
        z_s[3 * G + c] = a3 + z3;
        __syncthreads();

        const float zi = z_s[r * G + j];
        const float zf = z_s[r * G + H + j];
        const float zg = z_s[r * G + 2 * H + j];
        const float zo = z_s[r * G + 3 * H + j];
        const float ig = sigmoidf_(zi);
        const float fg = sigmoidf_(zf);
        const float gg = tanhf(zg);
        const float og = sigmoidf_(zo);
        c_st = fmaf(fg, c_st, ig * gg);
        h_carry = og * tanhf(c_st);
        h_s[j * RPB + r] = h_carry;
        if (STORE_ALL)
            h_all[((size_t)(b0 + r) * TT + t) * H + j] = h_carry;
        __syncthreads();   // h_s / z_s ready for next step
    }

    if (!STORE_ALL)
        h_last[(b0 + r) * H + j] = h_carry;
}

// ---------------------------------------------------------------------------
// Final dense + sigmoid: out[b] = sigmoid(h2_last[b,:] @ Wd + bd)
// ---------------------------------------------------------------------------
__global__ void dense_kernel(const float* __restrict__ h_last,
                             const float* __restrict__ Wd,
                             const float* __restrict__ bd,
                             float* __restrict__ out)
{
    const int b = blockIdx.x * blockDim.x + threadIdx.x;
    if (b >= BATCH) return;
    float s = bd[0];
#pragma unroll
    for (int k = 0; k < H; ++k)
        s = fmaf(h_last[b * H + k], Wd[k], s);
    out[b] = 1.f / (1.f + __expf(-s));
}

// ---------------------------------------------------------------------------
extern "C" void kernel_launch(void* const* d_in, const int* in_sizes, int n_in,
                              void* d_out, int out_size)
{
    const float* x  = (const float*)d_in[0];
    const float* W1 = (const float*)d_in[1];
    const float* U1 = (const float*)d_in[2];
    const float* b1 = (const float*)d_in[3];
    const float* W2 = (const float*)d_in[4];
    const float* U2 = (const float*)d_in[5];
    const float* b2 = (const float*)d_in[6];
    const float* Wd = (const float*)d_in[7];
    const float* bd = (const float*)d_in[8];
    float* out = (float*)d_out;

    float *xw, *h1, *h2l;
    cudaGetSymbolAddress((void**)&xw,  g_xw);
    cudaGetSymbolAddress((void**)&h1,  g_h1);
    cudaGetSymbolAddress((void**)&h2l, g_h2last);

    const int SMEM_LSTM = (H * G + H * RPB + RPB * G) * (int)sizeof(float); // 168000 B
    cudaFuncSetAttribute(lstm_kernel<true>,
                         cudaFuncAttributeMaxDynamicSharedMemorySize, SMEM_LSTM);
    cudaFuncSetAttribute(lstm_kernel<false>,
                         cudaFuncAttributeMaxDynamicSharedMemorySize, SMEM_LSTM);

    // Layer 1
    pregemm_kernel<FF><<<NTOK / GEMM_ROWS, GEMM_THREADS>>>(x, W1, b1, xw);
    lstm_kernel<true><<<LSTM_CTAS, LSTM_THREADS, SMEM_LSTM>>>(xw, U1, h1, nullptr);
    // Layer 2
    pregemm_kernel<H><<<NTOK / GEMM_ROWS, GEMM_THREADS>>>(h1, W2, b2, xw);
    lstm_kernel<false><<<LSTM_CTAS, LSTM_THREADS, SMEM_LSTM>>>(xw, U2, nullptr, h2l);
    // Head
    dense_kernel<<<2, 256>>>(h2l, Wd, bd, out);
}

// round 2
// speedup vs baseline: 1.4248x; 1.4248x over previous
#include <cuda_runtime.h>
#include <math.h>
#include <stddef.h>

#define H 100
#define G 400            // 4*H
#define BATCH 512
#define TT 1024
#define FF 64
#define NTOK (BATCH * TT)        // 524288
#define RPB 4                    // batch rows per LSTM CTA
#define LSTM_CTAS (BATCH / RPB)  // 128
#define LSTM_THREADS 200         // 2 cols per thread
#define GEMM_ROWS 64
#define GEMM_THREADS 400
#define AS_STRIDE 72             // padded [k][row] stride: 72*4B = 288B, 16B aligned

typedef unsigned long long u64;

// Scratch (static device allocation: no cudaMalloc allowed)
__device__ float g_xw[(size_t)NTOK * G];   // 838.9 MB, reused by both layers
__device__ float g_h1[(size_t)NTOK * H];   // 209.7 MB
__device__ float g_h2last[BATCH * H];

// ---------------------------------------------------------------------------
// f32x2 packed-FMA helpers (sm_100+): 2 independent fp32 FMAs per instruction.
// ---------------------------------------------------------------------------
__device__ __forceinline__ u64 f2dup(float x)
{
    u64 r;
    asm("mov.b64 %0, {%1, %1};" : "=l"(r) : "f"(x));
    return r;
}
__device__ __forceinline__ void fma2(u64& d, u64 a, u64 b)
{
    asm("fma.rn.f32x2 %0, %1, %2, %0;" : "+l"(d) : "l"(a), "l"(b));
}
__device__ __forceinline__ float2 unpk(u64 v)
{
    float2 r;
    asm("mov.b64 {%0, %1}, %2;" : "=f"(r.x), "=f"(r.y) : "l"(v));
    return r;
}

__device__ __forceinline__ float sigmoidf_(float x)
{
    return 1.f / (1.f + __expf(-x));
}

// ---------------------------------------------------------------------------
// Pre-activation GEMM: out[N,400] = A[N,K] @ Wm[K,400] + bias
// A tile transposed into SMEM as [k][row] (stride 72), row-pairs packed into
// f32x2 accumulators: per k = 1 LDG(w) + 1 dup + 16 bcast LDS.128 + 32 FFMA2.
// ---------------------------------------------------------------------------
template <int K>
__global__ void __launch_bounds__(GEMM_THREADS, 1)
pregemm_kernel(const float* __restrict__ A, const float* __restrict__ Wm,
               const float* __restrict__ bias, float* __restrict__ out)
{
    __shared__ __align__(16) float A_s[K * AS_STRIDE];
    const int tid = threadIdx.x;
    const size_t row0 = (size_t)blockIdx.x * GEMM_ROWS;

    // coalesced read, transposed (mildly conflicted) store
    const float* Atile = A + row0 * K;
    for (int i = tid; i < GEMM_ROWS * K; i += GEMM_THREADS) {
        const int r = i / K;
        const int k = i % K;
        A_s[k * AS_STRIDE + r] = Atile[i];
    }
    __syncthreads();

    const int c = tid;  // output column, 0..399
    u64 acc[GEMM_ROWS / 2];
#pragma unroll
    for (int p = 0; p < GEMM_ROWS / 2; ++p) acc[p] = 0ull;

    float w_next = Wm[c];
    for (int k = 0; k < K; ++k) {
        const float w = w_next;
        if (k + 1 < K) w_next = Wm[(k + 1) * G + c];
        const u64 wd = f2dup(w);
        const float* ak = &A_s[k * AS_STRIDE];
#pragma unroll
        for (int q = 0; q < GEMM_ROWS / 4; ++q) {
            const ulonglong2 ap = *(const ulonglong2*)(ak + q * 4); // rows 4q..4q+3
            fma2(acc[q * 2 + 0], ap.x, wd);
            fma2(acc[q * 2 + 1], ap.y, wd);
        }
    }

    const float bc = bias[c];
#pragma unroll
    for (int p = 0; p < GEMM_ROWS / 2; ++p) {
        const float2 v = unpk(acc[p]);
        out[(row0 + 2 * p + 0) * G + c] = v.x + bc;
        out[(row0 + 2 * p + 1) * G + c] = v.y + bc;
    }
}

// ---------------------------------------------------------------------------
// Persistent LSTM layer: one CTA owns RPB=4 batch rows for all T steps.
// 200 threads, each computes 2 adjacent z-columns for all 4 rows.
// SMEM: U [100x400] (160KB), h [k][r] (float4 per k), z [4x400].
// Per k: LDS.64(U pair) + LDS.128(h quad) + 2 dup + 4 FFMA2.
// ---------------------------------------------------------------------------
template <bool STORE_ALL>
__global__ void __launch_bounds__(LSTM_THREADS, 1)
lstm_kernel(const float* __restrict__ zpre,   // [B,T,G]
            const float* __restrict__ U,      // [H,G]
            float* __restrict__ h_all,        // [B,T,H] (layer 1)
            float* __restrict__ h_last)       // [B,H]   (layer 2)
{
    extern __shared__ __align__(16) float smem[];
    float* U_s = smem;                         // H*G   = 40000 floats
    float* h_s = smem + H * G;                 // [k][r], H*4 = 400 floats
    float* z_s = smem + H * G + H * RPB;       // [r][c], 4*400 floats

    const int tid = threadIdx.x;               // 0..199
    const int b0  = blockIdx.x * RPB;

    {   // vectorized U load (40000 floats = 10000 float4)
        const float4* Uv = (const float4*)U;
        float4* Usv = (float4*)U_s;
        for (int i = tid; i < (H * G) / 4; i += LSTM_THREADS) Usv[i] = Uv[i];
    }
    for (int i = tid; i < H * RPB; i += LSTM_THREADS) h_s[i] = 0.f;

    const int c0 = 2 * tid;      // z-phase column pair
    const int j  = tid % H;      // gate-phase hidden index
    const int r0 = tid / H;      // gate-phase: rows r0 and r0+2
    float cs0 = 0.f, cs1 = 0.f;
    float hv0 = 0.f, hv1 = 0.f;
    __syncthreads();

    const size_t bstride = (size_t)TT * G;
    const float* zp = zpre + (size_t)b0 * bstride + c0;

    for (int t = 0; t < TT; ++t) {
        // pre-activation loads (issued early, consumed after the matvec)
        const float2 zr0 = *(const float2*)(zp);
        const float2 zr1 = *(const float2*)(zp + bstride);
        const float2 zr2 = *(const float2*)(zp + 2 * bstride);
        const float2 zr3 = *(const float2*)(zp + 3 * bstride);

        u64 a00 = 0ull, a10 = 0ull, a01 = 0ull, a11 = 0ull; // [rowpair][col]
#pragma unroll 20
        for (int k = 0; k < H; ++k) {
            const float2 u = *(const float2*)&U_s[k * G + c0];
            const ulonglong2 hp = *(const ulonglong2*)&h_s[k * RPB]; // (h0,h1),(h2,h3)
            const u64 d0 = f2dup(u.x);
            const u64 d1 = f2dup(u.y);
            fma2(a00, hp.x, d0);
            fma2(a10, hp.y, d0);
            fma2(a01, hp.x, d1);
            fma2(a11, hp.y, d1);
        }
        const float2 p00 = unpk(a00);  // (row0,row1) col c0
        const float2 p10 = unpk(a10);  // (row2,row3) col c0
        const float2 p01 = unpk(a01);  // (row0,row1) col c0+1
        const float2 p11 = unpk(a11);  // (row2,row3) col c0+1
        *(float2*)&z_s[0 * G + c0] = make_float2(p00.x + zr0.x, p01.x + zr0.y);
        *(float2*)&z_s[1 * G + c0] = make_float2(p00.y + zr1.x, p01.y + zr1.y);
        *(float2*)&z_s[2 * G + c0] = make_float2(p10.x + zr2.x, p11.x + zr2.y);
        *(float2*)&z_s[3 * G + c0] = make_float2(p10.y + zr3.x, p11.y + zr3.y);
        __syncthreads();

        // gate phase: rows r0 and r0+2 for hidden index j
        {
            const int row = r0;
            const float ig = sigmoidf_(z_s[row * G + j]);
            const float fg = sigmoidf_(z_s[row * G + H + j]);
            const float gg = tanhf(z_s[row * G + 2 * H + j]);
            const float og = sigmoidf_(z_s[row * G + 3 * H + j]);
            cs0 = fmaf(fg, cs0, ig * gg);
            hv0 = og * tanhf(cs0);
            h_s[j * RPB + row] = hv0;
            if (STORE_ALL)
                h_all[((size_t)(b0 + row) * TT + t) * H + j] = hv0;
        }
        {
            const int row = r0 + 2;
            const float ig = sigmoidf_(z_s[row * G + j]);
            const float fg = sigmoidf_(z_s[row * G + H + j]);
            const float gg = tanhf(z_s[row * G + 2 * H + j]);
            const float og = sigmoidf_(z_s[row * G + 3 * H + j]);
            cs1 = fmaf(fg, cs1, ig * gg);
            hv1 = og * tanhf(cs1);
            h_s[j * RPB + row] = hv1;
            if (STORE_ALL)
                h_all[((size_t)(b0 + row) * TT + t) * H + j] = hv1;
        }
        __syncthreads();
        zp += G;
    }

    if (!STORE_ALL) {
        h_last[(b0 + r0) * H + j]     = hv0;
        h_last[(b0 + r0 + 2) * H + j] = hv1;
    }
}

// ---------------------------------------------------------------------------
// Final dense + sigmoid: out[b] = sigmoid(h2_last[b,:] @ Wd + bd)
// ---------------------------------------------------------------------------
__global__ void dense_kernel(const float* __restrict__ h_last,
                             const float* __restrict__ Wd,
                             const float* __restrict__ bd,
                             float* __restrict__ out)
{
    const int b = blockIdx.x * blockDim.x + threadIdx.x;
    if (b >= BATCH) return;
    float s = bd[0];
#pragma unroll
    for (int k = 0; k < H; ++k)
        s = fmaf(h_last[b * H + k], Wd[k], s);
    out[b] = 1.f / (1.f + __expf(-s));
}

// ---------------------------------------------------------------------------
extern "C" void kernel_launch(void* const* d_in, const int* in_sizes, int n_in,
                              void* d_out, int out_size)
{
    const float* x  = (const float*)d_in[0];
    const float* W1 = (const float*)d_in[1];
    const float* U1 = (const float*)d_in[2];
    const float* b1 = (const float*)d_in[3];
    const float* W2 = (const float*)d_in[4];
    const float* U2 = (const float*)d_in[5];
    const float* b2 = (const float*)d_in[6];
    const float* Wd = (const float*)d_in[7];
    const float* bd = (const float*)d_in[8];
    float* out = (float*)d_out;

    float *xw, *h1, *h2l;
    cudaGetSymbolAddress((void**)&xw,  g_xw);
    cudaGetSymbolAddress((void**)&h1,  g_h1);
    cudaGetSymbolAddress((void**)&h2l, g_h2last);

    const int SMEM_LSTM = (H * G + H * RPB + RPB * G) * (int)sizeof(float); // 168000 B
    cudaFuncSetAttribute(lstm_kernel<true>,
                         cudaFuncAttributeMaxDynamicSharedMemorySize, SMEM_LSTM);
    cudaFuncSetAttribute(lstm_kernel<false>,
                         cudaFuncAttributeMaxDynamicSharedMemorySize, SMEM_LSTM);

    // Layer 1
    pregemm_kernel<FF><<<NTOK / GEMM_ROWS, GEMM_THREADS>>>(x, W1, b1, xw);
    lstm_kernel<true><<<LSTM_CTAS, LSTM_THREADS, SMEM_LSTM>>>(xw, U1, h1, nullptr);
    // Layer 2
    pregemm_kernel<H><<<NTOK / GEMM_ROWS, GEMM_THREADS>>>(h1, W2, b2, xw);
    lstm_kernel<false><<<LSTM_CTAS, LSTM_THREADS, SMEM_LSTM>>>(xw, U2, nullptr, h2l);
    // Head
    dense_kernel<<<2, 256>>>(h2l, Wd, bd, out);
}

// round 3
// speedup vs baseline: 1.4611x; 1.0255x over previous
#include <cuda_runtime.h>
#include <math.h>
#include <stddef.h>

#define H 100
#define HM 50            // H/2 (k-pairs)
#define G 400            // 4*H
#define BATCH 512
#define TT 1024
#define FF 64
#define NTOK (BATCH * TT)        // 524288
#define RPB 4                    // batch rows per LSTM CTA
#define LSTM_CTAS (BATCH / RPB)  // 128
#define LSTM_THREADS 400         // 1 col per thread
#define GEMM_ROWS 64
#define GEMM_THREADS 400
#define AS_STRIDE 72             // padded [k][row] stride for pregemm

typedef unsigned long long u64;

// Scratch (static device allocation: no cudaMalloc allowed)
__device__ float g_xw[(size_t)NTOK * G];   // 838.9 MB, reused by both layers
__device__ float g_h1[(size_t)NTOK * H];   // 209.7 MB
__device__ float g_h2last[BATCH * H];

// ---------------------------------------------------------------------------
// f32x2 packed-FMA helpers (sm_100+)
// ---------------------------------------------------------------------------
__device__ __forceinline__ u64 f2dup(float x)
{
    u64 r;
    asm("mov.b64 %0, {%1, %1};" : "=l"(r) : "f"(x));
    return r;
}
__device__ __forceinline__ u64 f2pack(float lo, float hi)
{
    u64 r;
    asm("mov.b64 %0, {%1, %2};" : "=l"(r) : "f"(lo), "f"(hi));
    return r;
}
__device__ __forceinline__ void fma2(u64& d, u64 a, u64 b)
{
    asm("fma.rn.f32x2 %0, %1, %2, %0;" : "+l"(d) : "l"(a), "l"(b));
}
__device__ __forceinline__ float2 unpk(u64 v)
{
    float2 r;
    asm("mov.b64 {%0, %1}, %2;" : "=f"(r.x), "=f"(r.y) : "l"(v));
    return r;
}

// ---------------------------------------------------------------------------
// Fast transcendentals: MUFU ex2/rcp (abs err ~1e-6, far under 1e-3 budget)
// ---------------------------------------------------------------------------
#define LOG2E 1.4426950408889634f
__device__ __forceinline__ float ex2a(float x)
{
    float r;
    asm("ex2.approx.f32 %0, %1;" : "=f"(r) : "f"(x));
    return r;
}
__device__ __forceinline__ float rcpa(float x)
{
    float r;
    asm("rcp.approx.f32 %0, %1;" : "=f"(r) : "f"(x));
    return r;
}
__device__ __forceinline__ float fast_sig(float x)
{
    return rcpa(1.f + ex2a(-x * LOG2E));             // 1/(1+e^-x)
}
__device__ __forceinline__ float fast_tanh(float x)
{
    // tanh(x) = 2*sigmoid(2x) - 1
    return fmaf(2.f, rcpa(1.f + ex2a(-2.f * LOG2E * x)), -1.f);
}

// ---------------------------------------------------------------------------
// Pre-activation GEMM: out[N,400] = A[N,K] @ Wm[K,400] + bias  (unchanged)
// ---------------------------------------------------------------------------
template <int K>
__global__ void __launch_bounds__(GEMM_THREADS, 1)
pregemm_kernel(const float* __restrict__ A, const float* __restrict__ Wm,
               const float* __restrict__ bias, float* __restrict__ out)
{
    __shared__ __align__(16) float A_s[K * AS_STRIDE];
    const int tid = threadIdx.x;
    const size_t row0 = (size_t)blockIdx.x * GEMM_ROWS;

    const float* Atile = A + row0 * K;
    for (int i = tid; i < GEMM_ROWS * K; i += GEMM_THREADS) {
        const int r = i / K;
        const int k = i % K;
        A_s[k * AS_STRIDE + r] = Atile[i];
    }
    __syncthreads();

    const int c = tid;
    u64 acc[GEMM_ROWS / 2];
#pragma unroll
    for (int p = 0; p < GEMM_ROWS / 2; ++p) acc[p] = 0ull;

    float w_next = Wm[c];
    for (int k = 0; k < K; ++k) {
        const float w = w_next;
        if (k + 1 < K) w_next = Wm[(k + 1) * G + c];
        const u64 wd = f2dup(w);
        const float* ak = &A_s[k * AS_STRIDE];
#pragma unroll
        for (int q = 0; q < GEMM_ROWS / 4; ++q) {
            const ulonglong2 ap = *(const ulonglong2*)(ak + q * 4);
            fma2(acc[q * 2 + 0], ap.x, wd);
            fma2(acc[q * 2 + 1], ap.y, wd);
        }
    }

    const float bc = bias[c];
#pragma unroll
    for (int p = 0; p < GEMM_ROWS / 2; ++p) {
        const float2 v = unpk(acc[p]);
        out[(row0 + 2 * p + 0) * G + c] = v.x + bc;
        out[(row0 + 2 * p + 1) * G + c] = v.y + bc;
    }
}

// ---------------------------------------------------------------------------
// Persistent LSTM layer: one CTA owns RPB=4 batch rows for all T steps.
// 400 threads, 1 column each. U held in 50 packed u64 registers per thread
// (k-pairs), h kept in SMEM as u64 (h[2m][r], h[2m+1][r]) so the matvec is
// per m: 2x LDS.128 broadcast + 4 FFMA2 — no dup MOVs, no U SMEM traffic.
// Accumulator lanes = (even-k, odd-k) partial sums; summed at the end.
// ---------------------------------------------------------------------------
template <bool STORE_ALL>
__global__ void __launch_bounds__(LSTM_THREADS, 1)
lstm_kernel(const float* __restrict__ zpre,   // [B,T,G]
            const float* __restrict__ U,      // [H,G]
            float* __restrict__ h_all,        // [B,T,H] (layer 1)
            float* __restrict__ h_last)       // [B,H]   (layer 2)
{
    __shared__ __align__(16) u64 h2_s[HM * RPB];   // [m][r] packed k-pairs
    __shared__ float z_s[RPB * G];                 // [r][c]

    const int tid = threadIdx.x;               // 0..399
    const int b0  = blockIdx.x * RPB;
    const int c   = tid;                       // matvec column
    const int row = tid / H;                   // gate-phase row (0..3)
    const int j   = tid % H;                   // gate-phase hidden index

    // U k-pairs into registers (fully unrolled -> stays in regs)
    u64 U_pk[HM];
#pragma unroll
    for (int m = 0; m < HM; ++m)
        U_pk[m] = f2pack(U[(2 * m) * G + c], U[(2 * m + 1) * G + c]);

    if (tid < HM * RPB) h2_s[tid] = 0ull;

    float cs = 0.f, hv = 0.f;
    __syncthreads();

    const size_t bstride = (size_t)TT * G;
    const float* zp = zpre + (size_t)b0 * bstride + c;

    // prefetch step 0 pre-activations
    float zr0 = zp[0];
    float zr1 = zp[bstride];
    float zr2 = zp[2 * bstride];
    float zr3 = zp[3 * bstride];

    for (int t = 0; t < TT; ++t) {
        u64 a0 = 0ull, a1 = 0ull, a2 = 0ull, a3 = 0ull;
#pragma unroll
        for (int m = 0; m < HM; ++m) {
            const ulonglong2 h01 = *(const ulonglong2*)&h2_s[m * RPB];     // rows 0,1
            const ulonglong2 h23 = *(const ulonglong2*)&h2_s[m * RPB + 2]; // rows 2,3
            fma2(a0, h01.x, U_pk[m]);
            fma2(a1, h01.y, U_pk[m]);
            fma2(a2, h23.x, U_pk[m]);
            fma2(a3, h23.y, U_pk[m]);
        }
        const float2 s0 = unpk(a0);
        const float2 s1 = unpk(a1);
        const float2 s2 = unpk(a2);
        const float2 s3 = unpk(a3);
        z_s[0 * G + c] = (s0.x + s0.y) + zr0;
        z_s[1 * G + c] = (s1.x + s1.y) + zr1;
        z_s[2 * G + c] = (s2.x + s2.y) + zr2;
        z_s[3 * G + c] = (s3.x + s3.y) + zr3;

        // prefetch next step's pre-activations (hidden under gates + matvec)
        if (t + 1 < TT) {
            zp += G;
            zr0 = zp[0];
            zr1 = zp[bstride];
            zr2 = zp[2 * bstride];
            zr3 = zp[3 * bstride];
        }
        __syncthreads();

        // gate phase: one (row, j) per thread
        const float ig = fast_sig(z_s[row * G + j]);
        const float fg = fast_sig(z_s[row * G + H + j]);
        const float gg = fast_tanh(z_s[row * G + 2 * H + j]);
        const float og = fast_sig(z_s[row * G + 3 * H + j]);
        cs = fmaf(fg, cs, ig * gg);
        hv = og * fast_tanh(cs);

        // write h into packed (even-k, odd-k) u64 layout: float element
        ((float*)h2_s)[((j >> 1) * RPB + row) * 2 + (j & 1)] = hv;
        if (STORE_ALL)
            h_all[((size_t)(b0 + row) * TT + t) * H + j] = hv;
        __syncthreads();
    }

    if (!STORE_ALL)
        h_last[(b0 + row) * H + j] = hv;
}

// ---------------------------------------------------------------------------
// Final dense + sigmoid
// ---------------------------------------------------------------------------
__global__ void dense_kernel(const float* __restrict__ h_last,
                             const float* __restrict__ Wd,
                             const float* __restrict__ bd,
                             float* __restrict__ out)
{
    const int b = blockIdx.x * blockDim.x + threadIdx.x;
    if (b >= BATCH) return;
    float s = bd[0];
#pragma unroll
    for (int k = 0; k < H; ++k)
        s = fmaf(h_last[b * H + k], Wd[k], s);
    out[b] = 1.f / (1.f + __expf(-s));
}

// ---------------------------------------------------------------------------
extern "C" void kernel_launch(void* const* d_in, const int* in_sizes, int n_in,
                              void* d_out, int out_size)
{
    const float* x  = (const float*)d_in[0];
    const float* W1 = (const float*)d_in[1];
    const float* U1 = (const float*)d_in[2];
    const float* b1 = (const float*)d_in[3];
    const float* W2 = (const float*)d_in[4];
    const float* U2 = (const float*)d_in[5];
    const float* b2 = (const float*)d_in[6];
    const float* Wd = (const float*)d_in[7];
    const float* bd = (const float*)d_in[8];
    float* out = (float*)d_out;

    float *xw, *h1, *h2l;
    cudaGetSymbolAddress((void**)&xw,  g_xw);
    cudaGetSymbolAddress((void**)&h1,  g_h1);
    cudaGetSymbolAddress((void**)&h2l, g_h2last);

    // Layer 1
    pregemm_kernel<FF><<<NTOK / GEMM_ROWS, GEMM_THREADS>>>(x, W1, b1, xw);
    lstm_kernel<true><<<LSTM_CTAS, LSTM_THREADS>>>(xw, U1, h1, nullptr);
    // Layer 2
    pregemm_kernel<H><<<NTOK / GEMM_ROWS, GEMM_THREADS>>>(h1, W2, b2, xw);
    lstm_kernel<false><<<LSTM_CTAS, LSTM_THREADS>>>(xw, U2, nullptr, h2l);
    // Head
    dense_kernel<<<2, 256>>>(h2l, Wd, bd, out);
}

// round 5
// speedup vs baseline: 1.5475x; 1.0591x over previous
#include <cuda_runtime.h>
#include <math.h>
#include <stddef.h>

#define H 100
#define HM 50            // H/2 (k-pairs)
#define HMH 25           // k-pairs per half
#define G 400            // 4*H
#define BATCH 512
#define TT 1024
#define FF 64
#define NTOK (BATCH * TT)        // 524288
#define RPB 4                    // batch rows per LSTM CTA
#define LSTM_CTAS (BATCH / RPB)  // 128
#define LSTM_THREADS 800         // (column, k-half) per thread
#define GEMM_ROWS 32
#define GEMM_THREADS 400
#define AS_STRIDE 40             // padded [k][row] stride for pregemm (160B)

typedef unsigned long long u64;

// Scratch (static device allocation: no cudaMalloc allowed)
__device__ float g_xw[(size_t)NTOK * G];   // 838.9 MB, reused by both layers
__device__ float g_h1[(size_t)NTOK * H];   // 209.7 MB
__device__ float g_h2last[BATCH * H];

// ---------------------------------------------------------------------------
// f32x2 packed-FMA helpers (sm_100+)
// ---------------------------------------------------------------------------
__device__ __forceinline__ u64 f2dup(float x)
{
    u64 r;
    asm("mov.b64 %0, {%1, %1};" : "=l"(r) : "f"(x));
    return r;
}
__device__ __forceinline__ u64 f2pack(float lo, float hi)
{
    u64 r;
    asm("mov.b64 %0, {%1, %2};" : "=l"(r) : "f"(lo), "f"(hi));
    return r;
}
__device__ __forceinline__ void fma2(u64& d, u64 a, u64 b)
{
    asm("fma.rn.f32x2 %0, %1, %2, %0;" : "+l"(d) : "l"(a), "l"(b));
}
__device__ __forceinline__ float2 unpk(u64 v)
{
    float2 r;
    asm("mov.b64 {%0, %1}, %2;" : "=f"(r.x), "=f"(r.y) : "l"(v));
    return r;
}

// ---------------------------------------------------------------------------
// Fast transcendentals: MUFU ex2/rcp (abs err ~1e-6, far under 1e-3 budget)
// ---------------------------------------------------------------------------
#define LOG2E 1.4426950408889634f
__device__ __forceinline__ float ex2a(float x)
{
    float r;
    asm("ex2.approx.f32 %0, %1;" : "=f"(r) : "f"(x));
    return r;
}
__device__ __forceinline__ float rcpa(float x)
{
    float r;
    asm("rcp.approx.f32 %0, %1;" : "=f"(r) : "f"(x));
    return r;
}
__device__ __forceinline__ float fast_sig(float x)
{
    return rcpa(1.f + ex2a(-x * LOG2E));             // 1/(1+e^-x)
}
__device__ __forceinline__ float fast_tanh(float x)
{
    // tanh(x) = 2*sigmoid(2x) - 1
    return fmaf(2.f, rcpa(1.f + ex2a(-2.f * LOG2E * x)), -1.f);
}

// ---------------------------------------------------------------------------
// Pre-activation GEMM: out[N,400] = A[N,K] @ Wm[K,400] + bias
// ROWS=32 so accumulators fit 2 CTAs/SM (latency hiding across CTAs).
// Per k: 1 LDG(w) + 1 dup + 8 bcast LDS.128 + 16 FFMA2. k unrolled x2.
// ---------------------------------------------------------------------------
template <int K>
__global__ void __launch_bounds__(GEMM_THREADS, 2)
pregemm_kernel(const float* __restrict__ A, const float* __restrict__ Wm,
               const float* __restrict__ bias, float* __restrict__ out)
{
    __shared__ __align__(16) float A_s[K * AS_STRIDE];
    const int tid = threadIdx.x;
    const size_t row0 = (size_t)blockIdx.x * GEMM_ROWS;

    const float* Atile = A + row0 * K;
    for (int i = tid; i < GEMM_ROWS * K; i += GEMM_THREADS) {
        const int r = i / K;
        const int k = i % K;
        A_s[k * AS_STRIDE + r] = Atile[i];
    }
    __syncthreads();

    const int c = tid;
    u64 acc[GEMM_ROWS / 2];
#pragma unroll
    for (int p = 0; p < GEMM_ROWS / 2; ++p) acc[p] = 0ull;

    float w0n = Wm[c];
    float w1n = Wm[G + c];
    for (int k = 0; k < K; k += 2) {
        const float w0 = w0n;
        const float w1 = w1n;
        if (k + 2 < K) {
            w0n = Wm[(k + 2) * G + c];
            w1n = Wm[(k + 3) * G + c];
        }
        const u64 wd0 = f2dup(w0);
        const u64 wd1 = f2dup(w1);
        const float* ak0 = &A_s[k * AS_STRIDE];
        const float* ak1 = &A_s[(k + 1) * AS_STRIDE];
#pragma unroll
        for (int q = 0; q < GEMM_ROWS / 4; ++q) {
            const ulonglong2 a0 = *(const ulonglong2*)(ak0 + q * 4);
            fma2(acc[q * 2 + 0], a0.x, wd0);
            fma2(acc[q * 2 + 1], a0.y, wd0);
        }
#pragma unroll
        for (int q = 0; q < GEMM_ROWS / 4; ++q) {
            const ulonglong2 a1 = *(const ulonglong2*)(ak1 + q * 4);
            fma2(acc[q * 2 + 0], a1.x, wd1);
            fma2(acc[q * 2 + 1], a1.y, wd1);
        }
    }

    const float bc = bias[c];
#pragma unroll
    for (int p = 0; p < GEMM_ROWS / 2; ++p) {
        const float2 v = unpk(acc[p]);
        out[(row0 + 2 * p + 0) * G + c] = v.x + bc;
        out[(row0 + 2 * p + 1) * G + c] = v.y + bc;
    }
}

// ---------------------------------------------------------------------------
// Persistent LSTM layer: one CTA owns RPB=4 batch rows for all T steps.
// 800 threads = (k-half, column). Each thread: 25 k-pairs in registers
// (U_pk, 50 regs), per m: 2x LDS.128 broadcast(h) + 4 FFMA2. Each half
// writes partial z to its own SMEM region; gate threads (tid<400) sum the
// two halves — no extra barrier. 2 barriers/step, 25 warps for latency.
// ---------------------------------------------------------------------------
template <bool STORE_ALL>
__global__ void __launch_bounds__(LSTM_THREADS, 1)
lstm_kernel(const float* __restrict__ zpre,   // [B,T,G]
            const float* __restrict__ U,      // [H,G]
            float* __restrict__ h_all,        // [B,T,H] (layer 1)
            float* __restrict__ h_last)       // [B,H]   (layer 2)
{
    __shared__ __align__(16) u64 h2_s[HM * RPB];   // [m][r] packed k-pairs
    __shared__ float z_s[2 * RPB * G];             // [half][r][c]

    const int tid  = threadIdx.x;              // 0..799
    const int b0   = blockIdx.x * RPB;
    const int half = tid / G;                  // k-half (0 or 1)
    const int c    = tid % G;                  // column
    const int hbase = half * HMH * RPB;        // h2_s offset for this half
    const int row  = tid / H;                  // gate row (tid<400)
    const int j    = tid % H;                  // gate hidden index

    // 25 U k-pairs for this (half, c) into registers
    u64 U_pk[HMH];
#pragma unroll
    for (int m = 0; m < HMH; ++m) {
        const int k0 = 2 * (half * HMH + m);
        U_pk[m] = f2pack(U[k0 * G + c], U[(k0 + 1) * G + c]);
    }

    if (tid < HM * RPB) h2_s[tid] = 0ull;

    float cs = 0.f, hv = 0.f;
    __syncthreads();

    const size_t bstride = (size_t)TT * G;
    const float* zp = zpre + (size_t)b0 * bstride + c;

    // step-0 pre-activation prefetch (half 0 only; half 1 contributes 0)
    float zr0 = 0.f, zr1 = 0.f, zr2 = 0.f, zr3 = 0.f;
    if (half == 0) {
        zr0 = zp[0];
        zr1 = zp[bstride];
        zr2 = zp[2 * bstride];
        zr3 = zp[3 * bstride];
    }

    for (int t = 0; t < TT; ++t) {
        u64 a0 = 0ull, a1 = 0ull, a2 = 0ull, a3 = 0ull;
#pragma unroll
        for (int m = 0; m < HMH; ++m) {
            const ulonglong2 h01 = *(const ulonglong2*)&h2_s[hbase + m * RPB];     // rows 0,1
            const ulonglong2 h23 = *(const ulonglong2*)&h2_s[hbase + m * RPB + 2]; // rows 2,3
            fma2(a0, h01.x, U_pk[m]);
            fma2(a1, h01.y, U_pk[m]);
            fma2(a2, h23.x, U_pk[m]);
            fma2(a3, h23.y, U_pk[m]);
        }
        const float2 s0 = unpk(a0);
        const float2 s1 = unpk(a1);
        const float2 s2 = unpk(a2);
        const float2 s3 = unpk(a3);
        float* zh = z_s + half * (RPB * G);
        zh[0 * G + c] = (s0.x + s0.y) + zr0;
        zh[1 * G + c] = (s1.x + s1.y) + zr1;
        zh[2 * G + c] = (s2.x + s2.y) + zr2;
        zh[3 * G + c] = (s3.x + s3.y) + zr3;

        // prefetch next step's pre-activations (half 0)
        if (half == 0 && t + 1 < TT) {
            zp += G;
            zr0 = zp[0];
            zr1 = zp[bstride];
            zr2 = zp[2 * bstride];
            zr3 = zp[3 * bstride];
        }
        __syncthreads();

        // gate phase: threads 0..399 own one (row, j)
        if (tid < RPB * H) {
            const float zi = z_s[row * G + j]         + z_s[RPB * G + row * G + j];
            const float zf = z_s[row * G + H + j]     + z_s[RPB * G + row * G + H + j];
            const float zg = z_s[row * G + 2 * H + j] + z_s[RPB * G + row * G + 2 * H + j];
            const float zo = z_s[row * G + 3 * H + j] + z_s[RPB * G + row * G + 3 * H + j];
            const float ig = fast_sig(zi);
            const float fg = fast_sig(zf);
            const float gg = fast_tanh(zg);
            const float og = fast_sig(zo);
            cs = fmaf(fg, cs, ig * gg);
            hv = og * fast_tanh(cs);
            ((float*)h2_s)[((j >> 1) * RPB + row) * 2 + (j & 1)] = hv;
            if (STORE_ALL)
                h_all[((size_t)(b0 + row) * TT + t) * H + j] = hv;
        }
        __syncthreads();
    }

    if (!STORE_ALL && tid < RPB * H)
        h_last[(b0 + row) * H + j] = hv;
}

// ---------------------------------------------------------------------------
// Final dense + sigmoid
// ---------------------------------------------------------------------------
__global__ void dense_kernel(const float* __restrict__ h_last,
                             const float* __restrict__ Wd,
                             const float* __restrict__ bd,
                             float* __restrict__ out)
{
    const int b = blockIdx.x * blockDim.x + threadIdx.x;
    if (b >= BATCH) return;
    float s = bd[0];
#pragma unroll
    for (int k = 0; k < H; ++k)
        s = fmaf(h_last[b * H + k], Wd[k], s);
    out[b] = 1.f / (1.f + __expf(-s));
}

// ---------------------------------------------------------------------------
extern "C" void kernel_launch(void* const* d_in, const int* in_sizes, int n_in,
                              void* d_out, int out_size)
{
    const float* x  = (const float*)d_in[0];
    const float* W1 = (const float*)d_in[1];
    const float* U1 = (const float*)d_in[2];
    const float* b1 = (const float*)d_in[3];
    const float* W2 = (const float*)d_in[4];
    const float* U2 = (const float*)d_in[5];
    const float* b2 = (const float*)d_in[6];
    const float* Wd = (const float*)d_in[7];
    const float* bd = (const float*)d_in[8];
    float* out = (float*)d_out;

    float *xw, *h1, *h2l;
    cudaGetSymbolAddress((void**)&xw,  g_xw);
    cudaGetSymbolAddress((void**)&h1,  g_h1);
    cudaGetSymbolAddress((void**)&h2l, g_h2last);

    // Layer 1
    pregemm_kernel<FF><<<NTOK / GEMM_ROWS, GEMM_THREADS>>>(x, W1, b1, xw);
    lstm_kernel<true><<<LSTM_CTAS, LSTM_THREADS>>>(xw, U1, h1, nullptr);
    // Layer 2
    pregemm_kernel<H><<<NTOK / GEMM_ROWS, GEMM_THREADS>>>(h1, W2, b2, xw);
    lstm_kernel<false><<<LSTM_CTAS, LSTM_THREADS>>>(xw, U2, nullptr, h2l);
    // Head
    dense_kernel<<<2, 256>>>(h2l, Wd, bd, out);
}